// round 4
// baseline (speedup 1.0000x reference)
#include <cuda_runtime.h>
#include <cstdint>

// Problem constants
#define B_   4
#define TE   512
#define TD   256
#define DE   512
#define DD   512
#define U_   128
#define NROW_E (B_*TE)   // 2048 encoder rows
#define NROW_D (B_*TD)   // 1024 decoder rows
#define TT   8           // decoder-t tile per block in the fused kernel
#define CTX_OFF (NROW_D*DE)   // context elements before attn weights in d_out

// Scratch (static device globals: no allocation allowed)
__device__ float g_encT[U_ * NROW_E];   // enc projection, TRANSPOSED: [u][row]
__device__ float g_dec [NROW_D * U_];   // dec projection: [row][u]

__device__ __forceinline__ float tanh_fast(float x) {
    float y;
    asm("tanh.approx.f32 %0, %1;" : "=f"(y) : "f"(x));
    return y;
}

#define FMA_F32X2(d, a, b) \
    asm("fma.rn.f32x2 %0, %1, %2, %0;" : "+l"(d) : "l"(a), "l"(b))

// ---------------------------------------------------------------------------
// Kernel 1: both input projections.
//   enc_p[row,u] = enc[row,:] @ W1[:,u] + b1[u]   (stored transposed [u][row])
//   dec_p[row,u] = dec[row,:] @ W2[:,u] + b2[u]   (stored [row][u])
// Block: 16 rows x 128 u, 256 threads (each thread: 8 rows, 1 u).
// ---------------------------------------------------------------------------
__global__ __launch_bounds__(256) void proj_kernel(
    const float* __restrict__ enc, const float* __restrict__ dec,
    const float* __restrict__ W1, const float* __restrict__ b1,
    const float* __restrict__ W2, const float* __restrict__ b2)
{
    __shared__ float sX[16][512];

    const int ENC_BLOCKS = NROW_E / 16;   // 128
    bool isDec = (blockIdx.x >= ENC_BLOCKS);
    int blk = isDec ? (blockIdx.x - ENC_BLOCKS) : blockIdx.x;
    int rowBase = blk * 16;

    const float* X    = isDec ? dec : enc;
    const float* W    = isDec ? W2  : W1;
    const float* bias = isDec ? b2  : b1;

    // load 16 rows of X (16*512 floats) into smem, vectorized
    const float4* Xv  = (const float4*)(X + (size_t)rowBase * 512);
    float4*       sXv = (float4*)&sX[0][0];
    for (int j = threadIdx.x; j < 16 * 128; j += 256) sXv[j] = Xv[j];
    __syncthreads();

    int u  = threadIdx.x & 127;
    int rg = threadIdx.x >> 7;   // 0 or 1 -> rows rg*8 .. rg*8+7

    float acc[8];
    float bv = bias[u];
#pragma unroll
    for (int i = 0; i < 8; i++) acc[i] = bv;

    const float* Wp = W + u;
#pragma unroll 4
    for (int k = 0; k < 512; k++) {
        float wv = Wp[(size_t)k * U_];          // coalesced across u
#pragma unroll
        for (int i = 0; i < 8; i++)
            acc[i] += sX[rg * 8 + i][k] * wv;   // smem broadcast
    }

    if (isDec) {
#pragma unroll
        for (int i = 0; i < 8; i++)
            g_dec[(size_t)(rowBase + rg * 8 + i) * U_ + u] = acc[i];
    } else {
#pragma unroll
        for (int i = 0; i < 8; i++)
            g_encT[(size_t)u * NROW_E + rowBase + rg * 8 + i] = acc[i];
    }
}

// ---------------------------------------------------------------------------
// Kernel 2: fused score + softmax + context for a (b, 8-t tile).
// Grid: B * (TD/TT) = 128 blocks, 512 threads (thread = one e, then one d).
// ---------------------------------------------------------------------------
__global__ __launch_bounds__(512) void attn_kernel(
    const float* __restrict__ enc,
    const float* __restrict__ Vw,
    float* __restrict__ out)
{
    __shared__ float sdp[TT][U_];            // dec_p tile
    __shared__ float sV[U_];
    __shared__ float sred[TT * 16];
    __shared__ float smax[TT];
    __shared__ float ssum[TT];
    __shared__ __align__(16) float s_w[TE][TT];   // attn weights [e][t]

    int b  = blockIdx.x >> 5;                // / (TD/TT = 32)
    int t0 = (blockIdx.x & 31) * TT;
    int tid = threadIdx.x;

    // load dec_p tile (8 rows x 128) + V
    for (int j = tid; j < TT * U_; j += 512)
        ((float*)sdp)[j] = g_dec[(size_t)(b * TD + t0) * U_ + j];
    if (tid < U_) sV[tid] = Vw[tid];
    __syncthreads();

    // ---- score phase: thread owns e = tid ----
    int e = tid;
    float acc[TT];
#pragma unroll
    for (int t = 0; t < TT; t++) acc[t] = 0.f;

    const float* ep = g_encT + (size_t)b * TE + e;
#pragma unroll 2
    for (int u = 0; u < U_; u++) {
        float ev = ep[(size_t)u * NROW_E];   // coalesced
        float vv = sV[u];
#pragma unroll
        for (int t = 0; t < TT; t++)
            acc[t] += vv * tanh_fast(ev + sdp[t][u]);
    }
    // (V_b dropped: softmax is shift-invariant, so it cancels in both outputs)

    // ---- softmax over e (block-wide), per t ----
    int lane = tid & 31, wid = tid >> 5;     // 16 warps

    // max
#pragma unroll
    for (int t = 0; t < TT; t++) {
        float v = acc[t];
#pragma unroll
        for (int o = 16; o; o >>= 1)
            v = fmaxf(v, __shfl_xor_sync(0xffffffffu, v, o));
        if (lane == 0) sred[t * 16 + wid] = v;
    }
    __syncthreads();
    if (wid < TT) {
        float v = (lane < 16) ? sred[wid * 16 + lane] : -3.0e38f;
#pragma unroll
        for (int o = 16; o; o >>= 1)
            v = fmaxf(v, __shfl_xor_sync(0xffffffffu, v, o));
        if (lane == 0) smax[wid] = v;
    }
    __syncthreads();

    // exp + sum
    float p[TT];
#pragma unroll
    for (int t = 0; t < TT; t++) {
        p[t] = __expf(acc[t] - smax[t]);
        float v = p[t];
#pragma unroll
        for (int o = 16; o; o >>= 1)
            v += __shfl_xor_sync(0xffffffffu, v, o);
        if (lane == 0) sred[t * 16 + wid] = v;
    }
    __syncthreads();
    if (wid < TT) {
        float v = (lane < 16) ? sred[wid * 16 + lane] : 0.f;
#pragma unroll
        for (int o = 16; o; o >>= 1)
            v += __shfl_xor_sync(0xffffffffu, v, o);
        if (lane == 0) ssum[wid] = v;
    }
    __syncthreads();

    // weights: store to smem [e][t] (for context) and to gmem output
    {
        float w[TT];
#pragma unroll
        for (int t = 0; t < TT; t++) w[t] = p[t] / ssum[t];
        *(float4*)&s_w[e][0] = make_float4(w[0], w[1], w[2], w[3]);
        *(float4*)&s_w[e][4] = make_float4(w[4], w[5], w[6], w[7]);
#pragma unroll
        for (int t = 0; t < TT; t++)
            out[CTX_OFF + (size_t)(b * TD + t0 + t) * TE + e] = w[t];
    }
    __syncthreads();

    // ---- context phase: thread owns d = tid ----
    // context[t,d] = sum_e w[t,e] * enc[b,e,d]; packed f32x2 FMA (2 t per op)
    int d = tid;
    const float* eb = enc + (size_t)b * TE * DE + d;

    unsigned long long cc[4];
#pragma unroll
    for (int j = 0; j < 4; j++) cc[j] = 0ULL;

#pragma unroll 4
    for (int ei = 0; ei < TE; ei++) {
        float ev = __ldg(eb + (size_t)ei * DE);  // coalesced, L2-resident
        unsigned long long evv;
        asm("mov.b64 %0, {%1, %2};" : "=l"(evv) : "f"(ev), "f"(ev));
        const ulonglong2* wr = (const ulonglong2*)&s_w[ei][0];
        ulonglong2 q0 = wr[0];   // (w0,w1),(w2,w3)
        ulonglong2 q1 = wr[1];   // (w4,w5),(w6,w7)
        FMA_F32X2(cc[0], q0.x, evv);
        FMA_F32X2(cc[1], q0.y, evv);
        FMA_F32X2(cc[2], q1.x, evv);
        FMA_F32X2(cc[3], q1.y, evv);
    }

    float c[TT];
#pragma unroll
    for (int j = 0; j < 4; j++) {
        float lo, hi;
        asm("mov.b64 {%0, %1}, %2;" : "=f"(lo), "=f"(hi) : "l"(cc[j]));
        c[2 * j]     = lo;
        c[2 * j + 1] = hi;
    }
#pragma unroll
    for (int t = 0; t < TT; t++)
        out[(size_t)(b * TD + t0 + t) * DE + d] = c[t];
}

// ---------------------------------------------------------------------------
extern "C" void kernel_launch(void* const* d_in, const int* in_sizes, int n_in,
                              void* d_out, int out_size)
{
    (void)in_sizes; (void)n_in; (void)out_size;
    const float* enc = (const float*)d_in[0];
    const float* dec = (const float*)d_in[1];
    const float* W1  = (const float*)d_in[2];
    const float* b1  = (const float*)d_in[3];
    const float* W2  = (const float*)d_in[4];
    const float* b2  = (const float*)d_in[5];
    const float* Vw  = (const float*)d_in[6];
    // d_in[7] = V_b: unused (cancels in softmax)
    float* out = (float*)d_out;

    proj_kernel<<<NROW_E / 16 + NROW_D / 16, 256>>>(enc, dec, W1, b1, W2, b2);
    attn_kernel<<<B_ * (TD / TT), 512>>>(enc, Vw, out);
}

// round 6
// speedup vs baseline: 1.3120x; 1.3120x over previous
#include <cuda_runtime.h>
#include <cstdint>

// Problem constants
#define B_   4
#define TE   512
#define TD   256
#define DE   512
#define DD   512
#define U_   128
#define NROW_E (B_*TE)   // 2048 encoder rows
#define NROW_D (B_*TD)   // 1024 decoder rows
#define TT   8           // decoder-t tile per block in the fused kernel
#define CTX_OFF (NROW_D*DE)   // context elements before attn weights in d_out

// Scratch (static device globals: no allocation allowed)
__device__ float g_encT[U_ * NROW_E];   // enc projection, TRANSPOSED: [u][row]
__device__ float g_dec [NROW_D * U_];   // dec projection: [row][u]

__device__ __forceinline__ float tanh_fast(float x) {
    float y;
    asm("tanh.approx.f32 %0, %1;" : "=f"(y) : "f"(x));
    return y;
}

#define FMA_F32X2(d, a, b) \
    asm("fma.rn.f32x2 %0, %1, %2, %0;" : "+l"(d) : "l"(a), "l"(b))

// ---------------------------------------------------------------------------
// Kernel 1: both input projections.
//   enc_p[row,u] = enc[row,:] @ W1[:,u] + b1[u]   (stored transposed [u][row])
//   dec_p[row,u] = dec[row,:] @ W2[:,u] + b2[u]   (stored [row][u])
// Block: 16 rows x 128 u, 256 threads (each thread: 8 rows, 1 u).
// ---------------------------------------------------------------------------
__global__ __launch_bounds__(256) void proj_kernel(
    const float* __restrict__ enc, const float* __restrict__ dec,
    const float* __restrict__ W1, const float* __restrict__ b1,
    const float* __restrict__ W2, const float* __restrict__ b2)
{
    __shared__ float sX[16][512];

    const int ENC_BLOCKS = NROW_E / 16;   // 128
    bool isDec = (blockIdx.x >= ENC_BLOCKS);
    int blk = isDec ? (blockIdx.x - ENC_BLOCKS) : blockIdx.x;
    int rowBase = blk * 16;

    const float* X    = isDec ? dec : enc;
    const float* W    = isDec ? W2  : W1;
    const float* bias = isDec ? b2  : b1;

    const float4* Xv  = (const float4*)(X + (size_t)rowBase * 512);
    float4*       sXv = (float4*)&sX[0][0];
    for (int j = threadIdx.x; j < 16 * 128; j += 256) sXv[j] = Xv[j];
    __syncthreads();

    int u  = threadIdx.x & 127;
    int rg = threadIdx.x >> 7;

    float acc[8];
    float bv = bias[u];
#pragma unroll
    for (int i = 0; i < 8; i++) acc[i] = bv;

    const float* Wp = W + u;
#pragma unroll 4
    for (int k = 0; k < 512; k++) {
        float wv = Wp[(size_t)k * U_];
#pragma unroll
        for (int i = 0; i < 8; i++)
            acc[i] += sX[rg * 8 + i][k] * wv;
    }

    if (isDec) {
#pragma unroll
        for (int i = 0; i < 8; i++)
            g_dec[(size_t)(rowBase + rg * 8 + i) * U_ + u] = acc[i];
    } else {
#pragma unroll
        for (int i = 0; i < 8; i++)
            g_encT[(size_t)u * NROW_E + rowBase + rg * 8 + i] = acc[i];
    }
}

// ---------------------------------------------------------------------------
// Kernel 2: fused score + softmax + context for a (b, 8-t tile).
// Grid: B * (TD/TT) = 128 blocks, 1024 threads (2 halves of 512).
//   Score:   thread = (e = tid&511, half = tid>>9); half owns 4 of the 8 t's.
//   Context: thread = (d = tid&511, half); half owns 256 of the 512 e's,
//            partials combined through s_w (reused after weights consumed).
// ---------------------------------------------------------------------------
__global__ __launch_bounds__(1024) void attn_kernel(
    const float* __restrict__ enc,
    const float* __restrict__ Vw,
    float* __restrict__ out)
{
    __shared__ float sdp[TT][U_];            // dec_p tile
    __shared__ float sV[U_];
    __shared__ float sred[TT * 16];
    __shared__ float smax[TT];
    __shared__ float ssum[TT];
    __shared__ __align__(16) float s_w[TE][TT];   // weights [e][t] -> later ctx partials [d][t]

    int b  = blockIdx.x >> 5;                // / (TD/TT = 32)
    int t0 = (blockIdx.x & 31) * TT;
    int tid  = threadIdx.x;
    int half = tid >> 9;                     // 0 or 1
    int eth  = tid & 511;                    // e (score) / d (context)

    // load dec_p tile (8 rows x 128) + V
    for (int j = tid; j < TT * U_; j += 1024)
        ((float*)sdp)[j] = g_dec[(size_t)(b * TD + t0) * U_ + j];
    if (tid < U_) sV[tid] = Vw[tid];
    __syncthreads();

    // ---- score phase: thread owns e = eth, t in [half*4, half*4+4) ----
    float acc[4];
#pragma unroll
    for (int t = 0; t < 4; t++) acc[t] = 0.f;

    const float* ep = g_encT + (size_t)b * TE + eth;
    const int tb = half * 4;
#pragma unroll 4
    for (int u = 0; u < U_; u++) {
        float ev = ep[(size_t)u * NROW_E];   // coalesced, L2-resident
        float vv = sV[u];
#pragma unroll
        for (int t = 0; t < 4; t++)
            acc[t] += vv * tanh_fast(ev + sdp[tb + t][u]);
    }
    // (V_b dropped: softmax is shift-invariant; cancels in both outputs)

    // ---- softmax over e (512 threads per half), per t ----
    int lane = tid & 31, wid = tid >> 5;     // 32 warps
    int wloc = wid & 15;                     // warp index within half

    // max
#pragma unroll
    for (int t = 0; t < 4; t++) {
        float v = acc[t];
#pragma unroll
        for (int o = 16; o; o >>= 1)
            v = fmaxf(v, __shfl_xor_sync(0xffffffffu, v, o));
        if (lane == 0) sred[(tb + t) * 16 + wloc] = v;
    }
    __syncthreads();
    if (wid < TT) {
        float v = (lane < 16) ? sred[wid * 16 + lane] : -3.0e38f;
#pragma unroll
        for (int o = 8; o; o >>= 1)
            v = fmaxf(v, __shfl_xor_sync(0xffffffffu, v, o));
        if (lane == 0) smax[wid] = v;
    }
    __syncthreads();

    // exp + sum
    float p[4];
#pragma unroll
    for (int t = 0; t < 4; t++) {
        p[t] = __expf(acc[t] - smax[tb + t]);
        float v = p[t];
#pragma unroll
        for (int o = 16; o; o >>= 1)
            v += __shfl_xor_sync(0xffffffffu, v, o);
        if (lane == 0) sred[(tb + t) * 16 + wloc] = v;
    }
    __syncthreads();
    if (wid < TT) {
        float v = (lane < 16) ? sred[wid * 16 + lane] : 0.f;
#pragma unroll
        for (int o = 8; o; o >>= 1)
            v += __shfl_xor_sync(0xffffffffu, v, o);
        if (lane == 0) ssum[wid] = v;
    }
    __syncthreads();

    // weights -> smem [e][t] (for context) and gmem output
    {
        float w[4];
#pragma unroll
        for (int t = 0; t < 4; t++) w[t] = p[t] / ssum[tb + t];
        *(float4*)&s_w[eth][tb] = make_float4(w[0], w[1], w[2], w[3]);
#pragma unroll
        for (int t = 0; t < 4; t++)
            out[CTX_OFF + (size_t)(b * TD + t0 + tb + t) * TE + eth] = w[t];
    }
    __syncthreads();

    // ---- context phase: thread owns d = eth, e-range [half*256, +256) ----
    // context[t,d] = sum_e w[t,e] * enc[b,e,d]; packed f32x2 FMA (2 t per op)
    const float* eb = enc + ((size_t)b * TE + half * 256) * DE + eth;

    unsigned long long cc[4];
#pragma unroll
    for (int j = 0; j < 4; j++) cc[j] = 0ULL;

#pragma unroll 4
    for (int ei = 0; ei < 256; ei++) {
        float ev = __ldg(eb + (size_t)ei * DE);     // coalesced, L2-resident
        unsigned long long evv;
        asm("mov.b64 %0, {%1, %2};" : "=l"(evv) : "f"(ev), "f"(ev));
        const ulonglong2* wr = (const ulonglong2*)&s_w[half * 256 + ei][0];
        ulonglong2 q0 = wr[0];   // (w0,w1),(w2,w3)
        ulonglong2 q1 = wr[1];   // (w4,w5),(w6,w7)
        FMA_F32X2(cc[0], q0.x, evv);
        FMA_F32X2(cc[1], q0.y, evv);
        FMA_F32X2(cc[2], q1.x, evv);
        FMA_F32X2(cc[3], q1.y, evv);
    }

    float c[TT];
#pragma unroll
    for (int j = 0; j < 4; j++) {
        float lo, hi;
        asm("mov.b64 {%0, %1}, %2;" : "=f"(lo), "=f"(hi) : "l"(cc[j]));
        c[2 * j]     = lo;
        c[2 * j + 1] = hi;
    }

    // combine the two e-half partials through s_w (weights no longer needed)
    __syncthreads();
    if (half == 1) {
        *(float4*)&s_w[eth][0] = make_float4(c[0], c[1], c[2], c[3]);
        *(float4*)&s_w[eth][4] = make_float4(c[4], c[5], c[6], c[7]);
    }
    __syncthreads();
    if (half == 0) {
        float4 o0 = *(float4*)&s_w[eth][0];
        float4 o1 = *(float4*)&s_w[eth][4];
        c[0] += o0.x; c[1] += o0.y; c[2] += o0.z; c[3] += o0.w;
        c[4] += o1.x; c[5] += o1.y; c[6] += o1.z; c[7] += o1.w;
#pragma unroll
        for (int t = 0; t < TT; t++)
            out[(size_t)(b * TD + t0 + t) * DE + eth] = c[t];
    }
}

// ---------------------------------------------------------------------------
extern "C" void kernel_launch(void* const* d_in, const int* in_sizes, int n_in,
                              void* d_out, int out_size)
{
    (void)in_sizes; (void)n_in; (void)out_size;
    const float* enc = (const float*)d_in[0];
    const float* dec = (const float*)d_in[1];
    const float* W1  = (const float*)d_in[2];
    const float* b1  = (const float*)d_in[3];
    const float* W2  = (const float*)d_in[4];
    const float* b2  = (const float*)d_in[5];
    const float* Vw  = (const float*)d_in[6];
    // d_in[7] = V_b: unused (cancels in softmax)
    float* out = (float*)d_out;

    proj_kernel<<<NROW_E / 16 + NROW_D / 16, 256>>>(enc, dec, W1, b1, W2, b2);
    attn_kernel<<<B_ * (TD / TT), 1024>>>(enc, Vw, out);
}